// round 1
// baseline (speedup 1.0000x reference)
#include <cuda_runtime.h>
#include <math.h>

#define NB 32
#define CC 256
#define HW 3136
#define GG 8
#define CG 32

#define PI_HALF 1.57079632679489662f

// ---------------- scratch (device globals; no allocations allowed) ----------
__device__ float g_gramp[2][NB][CC][CC];   // K-split Gram partials (16 MB)
__device__ float g_t7[NB][CC][CC];         // p7w * t5 / 56                (8 MB)
__device__ float g_rowsum[NB][CC];         // per-batch channel row sums
__device__ float g_wp3t[CC][CC];           // Wp3 transposed: [k][c]

// ---------------- packed f32x2 helpers --------------------------------------
__device__ __forceinline__ unsigned long long pack2(float f) {
    unsigned long long r;
    unsigned u = __float_as_uint(f);
    asm("mov.b64 %0, {%1, %2};" : "=l"(r) : "r"(u), "r"(u));
    return r;
}
__device__ __forceinline__ void fma2(unsigned long long& d,
                                     unsigned long long a, unsigned long long b) {
    asm("fma.rn.f32x2 %0, %1, %2, %0;" : "+l"(d) : "l"(a), "l"(b));
}
__device__ __forceinline__ float2 unpack2(unsigned long long v) {
    unsigned lo, hi;
    asm("mov.b64 {%0, %1}, %2;" : "=r"(lo), "=r"(hi) : "l"(v));
    return make_float2(__uint_as_float(lo), __uint_as_float(hi));
}

// 8x8 register tile FMA step: aRow -> 8 consecutive floats, bRow -> 8 consecutive floats
__device__ __forceinline__ void tile_fma(unsigned long long acc[8][4],
                                         const float* aRow, const float* bRow) {
    float4 a0 = *(const float4*)(aRow);
    float4 a1 = *(const float4*)(aRow + 4);
    ulonglong2 b0 = *(const ulonglong2*)(bRow);
    ulonglong2 b1 = *(const ulonglong2*)(bRow + 4);
    unsigned long long ap[8];
    ap[0] = pack2(a0.x); ap[1] = pack2(a0.y); ap[2] = pack2(a0.z); ap[3] = pack2(a0.w);
    ap[4] = pack2(a1.x); ap[5] = pack2(a1.y); ap[6] = pack2(a1.z); ap[7] = pack2(a1.w);
    unsigned long long bp[4];
    bp[0] = b0.x; bp[1] = b0.y; bp[2] = b1.x; bp[3] = b1.y;
#pragma unroll
    for (int i = 0; i < 8; i++) {
#pragma unroll
        for (int j = 0; j < 4; j++) fma2(acc[i][j], ap[i], bp[j]);
    }
}

__device__ __forceinline__ void row_to_float4(const unsigned long long* a, float s,
                                              float4& o0, float4& o1) {
    float2 p0 = unpack2(a[0]), p1 = unpack2(a[1]);
    float2 p2 = unpack2(a[2]), p3 = unpack2(a[3]);
    o0 = make_float4(p0.x * s, p0.y * s, p1.x * s, p1.y * s);
    o1 = make_float4(p2.x * s, p2.y * s, p3.x * s, p3.y * s);
}

// ---------------- kernel 1: transpose Wp3 ------------------------------------
__global__ void k_wp3t(const float* __restrict__ w) {
    int idx = blockIdx.x * 1024 + threadIdx.x;   // 64 blocks x 1024 = 65536
    int k = idx >> 8, c = idx & 255;
    g_wp3t[k][c] = w[c * 256 + k];
}

// ---------------- kernel 2: per-channel row sums -----------------------------
__global__ void k_rowsum(const float* __restrict__ x) {
    int n = blockIdx.y;
    int w = threadIdx.x >> 5, lane = threadIdx.x & 31;
    int c = blockIdx.x * 8 + w;
    const float* row = x + ((size_t)n * CC + c) * HW;
    float s = 0.f;
    for (int i = lane; i < HW; i += 32) s += row[i];
#pragma unroll
    for (int o = 16; o; o >>= 1) s += __shfl_down_sync(0xffffffffu, s, o);
    if (lane == 0) g_rowsum[n][c] = s;
}

// ---------------- kernel 3: Gram = x x^T per batch (K-split by 2) ------------
__global__ __launch_bounds__(256, 2) void k_gram(const float* __restrict__ x) {
    __shared__ float As[32][128];
    __shared__ float Bs[32][128];
    const int n  = blockIdx.z >> 1;
    const int ks = blockIdx.z & 1;
    const int c0 = blockIdx.y * 128;
    const int d0 = blockIdx.x * 128;
    const float* xb = x + (size_t)n * CC * HW;

    const int tid  = threadIdx.x;
    const int ty8  = (tid >> 4) * 8;   // row tile base within 128
    const int tx8  = (tid & 15) * 8;   // col tile base within 128
    const int lrow = tid & 127;        // load: which of the 128 rows
    const int lk   = (tid >> 7) * 16;  // load: k base (0 or 16)

    unsigned long long acc[8][4];
#pragma unroll
    for (int i = 0; i < 8; i++)
#pragma unroll
        for (int j = 0; j < 4; j++) acc[i][j] = 0ull;

    const int kbeg = ks * (HW / 2);
    const int kend = kbeg + (HW / 2);
    for (int k0 = kbeg; k0 < kend; k0 += 32) {
        float4 av[4], bv[4];
        const float* pa = xb + (size_t)(c0 + lrow) * HW + k0 + lk;
        const float* pb = xb + (size_t)(d0 + lrow) * HW + k0 + lk;
#pragma unroll
        for (int q = 0; q < 4; q++) {
            av[q] = *(const float4*)(pa + 4 * q);
            bv[q] = *(const float4*)(pb + 4 * q);
        }
        __syncthreads();
#pragma unroll
        for (int q = 0; q < 4; q++) {
            As[lk + 4 * q + 0][lrow] = av[q].x;
            As[lk + 4 * q + 1][lrow] = av[q].y;
            As[lk + 4 * q + 2][lrow] = av[q].z;
            As[lk + 4 * q + 3][lrow] = av[q].w;
            Bs[lk + 4 * q + 0][lrow] = bv[q].x;
            Bs[lk + 4 * q + 1][lrow] = bv[q].y;
            Bs[lk + 4 * q + 2][lrow] = bv[q].z;
            Bs[lk + 4 * q + 3][lrow] = bv[q].w;
        }
        __syncthreads();
#pragma unroll 8
        for (int k = 0; k < 32; k++)
            tile_fma(acc, &As[k][ty8], &Bs[k][tx8]);
    }

    float* gout = &g_gramp[ks][n][0][0];
#pragma unroll
    for (int i = 0; i < 8; i++) {
        int c = c0 + ty8 + i;
        float4 o0, o1;
        row_to_float4(acc[i], 1.0f, o0, o1);
        *(float4*)(gout + (size_t)c * CC + d0 + tx8)     = o0;
        *(float4*)(gout + (size_t)c * CC + d0 + tx8 + 4) = o1;
    }
}

// ---------------- kernel 4: t7 = p7w .* (B1 G B2^T + bias terms) / 56 --------
__global__ void k_t7(const float* __restrict__ Wg1, const float* __restrict__ bg1,
                     const float* __restrict__ Wg2, const float* __restrict__ bg2,
                     const float* __restrict__ p7w) {
    __shared__ float W1s[32][33], W2s[32][33], Gs[32][33], Ms[32][33];
    const int n = blockIdx.z, g = blockIdx.y, h = blockIdx.x;
    const int tx = threadIdx.x, ty = threadIdx.y;

    W1s[ty][tx] = Wg1[(g * 32 + ty) * 32 + tx];
    W2s[ty][tx] = Wg2[(h * 32 + ty) * 32 + tx];
    Gs[ty][tx]  = g_gramp[0][n][g * 32 + ty][h * 32 + tx]
                + g_gramp[1][n][g * 32 + ty][h * 32 + tx];
    __syncthreads();

    float m = 0.f;
#pragma unroll
    for (int i = 0; i < 32; i++) m += W1s[ty][i] * Gs[i][tx];

    float u = 0.f, v = 0.f;
#pragma unroll
    for (int i = 0; i < 32; i++) {
        u += W1s[ty][i] * g_rowsum[n][g * 32 + i];
        v += W2s[tx][i] * g_rowsum[n][h * 32 + i];
    }
    Ms[ty][tx] = m;
    __syncthreads();

    float t5 = 0.f;
#pragma unroll
    for (int j = 0; j < 32; j++) t5 += Ms[ty][j] * W2s[tx][j];

    const int c = g * 32 + ty, d = h * 32 + tx;
    const float b1 = bg1[c], b2 = bg2[d];
    t5 += b1 * v + u * b2 + (float)HW * b1 * b2;
    g_t7[n][c][d] = p7w[c * 256 + d] * t5 * (1.0f / 56.0f);
}

// ---------------- kernel 5: fused t3 / sin / max / output GEMM ---------------
// per block: 64-column stripe of one batch.
// stage 1: t6s[c][j] = max( (Wp3 x)[c,j] + bp3[c], sin(pi/2 * x[c,j]) )
// stage 2: out[d][j] = (1/16) * sum_c t7[n][c][d] * t6s[c][j]
#define SMEM_FUSED_BYTES ((256 * 64 + 16 * 256 + 16 * 64) * 4)

__global__ __launch_bounds__(256, 2) void k_fused(const float* __restrict__ x,
                                                  const float* __restrict__ bp3,
                                                  float* __restrict__ out) {
    extern __shared__ float sm[];
    float (*t6s)[64]  = (float(*)[64])sm;                         // 256 x 64
    float (*As)[256]  = (float(*)[256])(sm + 256 * 64);           // 16 x 256
    float (*Bs)[64]   = (float(*)[64])(sm + 256 * 64 + 16 * 256); // 16 x 64

    const int n    = blockIdx.y;
    const int col0 = blockIdx.x * 64;
    const float* xb = x + (size_t)n * CC * HW;

    const int tid = threadIdx.x;
    const int ty8 = (tid >> 3) * 8;   // output-row tile base (0..248)
    const int tx8 = (tid & 7) * 8;    // output-col tile base (0..56)
    const int ar  = tid >> 4;         // A-chunk load row (0..15)
    const int ac  = (tid & 15) * 4;   // A-chunk load col base
    const int br  = tid >> 4;         // B-chunk load row
    const int bc  = (tid & 15) * 4;   // B-chunk load col base

    unsigned long long acc[8][4];
#pragma unroll
    for (int i = 0; i < 8; i++)
#pragma unroll
        for (int j = 0; j < 4; j++) acc[i][j] = 0ull;

    // ---------------- stage 1: t3 = Wp3 @ x(stripe); sin written alongside ----
    for (int kc = 0; kc < 16; kc++) {
        const int k0 = kc * 16;
        float4 a4[4];
#pragma unroll
        for (int q = 0; q < 4; q++)
            a4[q] = *(const float4*)(&g_wp3t[k0 + ar][ac + 64 * q]);
        float4 b4 = *(const float4*)(xb + (size_t)(k0 + br) * HW + col0 + bc);
        __syncthreads();
#pragma unroll
        for (int q = 0; q < 4; q++)
            *(float4*)&As[ar][ac + 64 * q] = a4[q];
        *(float4*)&Bs[br][bc] = b4;
        float4 s4;
        s4.x = sinf(b4.x * PI_HALF);
        s4.y = sinf(b4.y * PI_HALF);
        s4.z = sinf(b4.z * PI_HALF);
        s4.w = sinf(b4.w * PI_HALF);
        *(float4*)&t6s[k0 + br][bc] = s4;
        __syncthreads();
#pragma unroll 8
        for (int k = 0; k < 16; k++)
            tile_fma(acc, &As[k][ty8], &Bs[k][tx8]);
    }

    // epilogue: t6 = max(t3 + bp3, sin)  (each thread owns exclusive cells)
#pragma unroll
    for (int i = 0; i < 8; i++) {
        const int c = ty8 + i;
        const float bias = __ldg(&bp3[c]);
#pragma unroll
        for (int j = 0; j < 4; j++) {
            float2 p = unpack2(acc[i][j]);
            float* t = &t6s[c][tx8 + 2 * j];
            t[0] = fmaxf(t[0], p.x + bias);
            t[1] = fmaxf(t[1], p.y + bias);
            acc[i][j] = 0ull;
        }
    }
    __syncthreads();

    // ---------------- stage 2: out = (1/16) t7^T @ t6 -------------------------
    const float* t7b = &g_t7[n][0][0];
    for (int kc = 0; kc < 16; kc++) {
        const int k0 = kc * 16;
        float4 a4[4];
#pragma unroll
        for (int q = 0; q < 4; q++)
            a4[q] = *(const float4*)(t7b + (size_t)(k0 + ar) * 256 + ac + 64 * q);
        __syncthreads();
#pragma unroll
        for (int q = 0; q < 4; q++)
            *(float4*)&As[ar][ac + 64 * q] = a4[q];
        __syncthreads();
#pragma unroll 8
        for (int k = 0; k < 16; k++)
            tile_fma(acc, &As[k][ty8], &t6s[k0 + k][tx8]);
    }

    float* ob = out + (size_t)n * CC * HW;
#pragma unroll
    for (int i = 0; i < 8; i++) {
        const int d = ty8 + i;
        float4 o0, o1;
        row_to_float4(acc[i], 1.0f / 16.0f, o0, o1);
        *(float4*)(ob + (size_t)d * HW + col0 + tx8)     = o0;
        *(float4*)(ob + (size_t)d * HW + col0 + tx8 + 4) = o1;
    }
}

// ---------------- launch ------------------------------------------------------
extern "C" void kernel_launch(void* const* d_in, const int* in_sizes, int n_in,
                              void* d_out, int out_size) {
    (void)in_sizes; (void)n_in; (void)out_size;
    const float* x   = (const float*)d_in[0];
    const float* Wp3 = (const float*)d_in[1];
    const float* bp3 = (const float*)d_in[2];
    const float* Wg1 = (const float*)d_in[3];
    const float* bg1 = (const float*)d_in[4];
    const float* Wg2 = (const float*)d_in[5];
    const float* bg2 = (const float*)d_in[6];
    const float* p7w = (const float*)d_in[7];
    float* out = (float*)d_out;

    cudaFuncSetAttribute(k_fused, cudaFuncAttributeMaxDynamicSharedMemorySize,
                         SMEM_FUSED_BYTES);

    k_wp3t<<<64, 1024>>>(Wp3);
    k_rowsum<<<dim3(32, 32), 256>>>(x);
    k_gram<<<dim3(2, 2, 64), 256>>>(x);
    k_t7<<<dim3(8, 8, 32), dim3(32, 32)>>>(Wg1, bg1, Wg2, bg2, p7w);
    k_fused<<<dim3(49, 32), 256, SMEM_FUSED_BYTES>>>(x, bp3, out);
}

// round 2
// speedup vs baseline: 1.0002x; 1.0002x over previous
#include <cuda_runtime.h>
#include <math.h>

#define NB 32
#define CC 256
#define HW 3136
#define GG 8
#define CG 32

#define PI_HALF 1.57079632679489662f

// ---------------- scratch (device globals; no allocations allowed) ----------
__device__ float g_gramp[2][NB][CC][CC];   // K-split Gram partials (16 MB)
__device__ float g_t7[NB][CC][CC];         // p7w * t5 / 56                (8 MB)
__device__ float g_rowsum[NB][CC];         // per-batch channel row sums
__device__ float g_wp3t[CC][CC];           // Wp3 transposed: [k][c]

// ---------------- packed f32x2 helpers --------------------------------------
__device__ __forceinline__ unsigned long long pack2(float f) {
    unsigned long long r;
    unsigned u = __float_as_uint(f);
    asm("mov.b64 %0, {%1, %2};" : "=l"(r) : "r"(u), "r"(u));
    return r;
}
__device__ __forceinline__ void fma2(unsigned long long& d,
                                     unsigned long long a, unsigned long long b) {
    asm("fma.rn.f32x2 %0, %1, %2, %0;" : "+l"(d) : "l"(a), "l"(b));
}
__device__ __forceinline__ float2 unpack2(unsigned long long v) {
    unsigned lo, hi;
    asm("mov.b64 {%0, %1}, %2;" : "=r"(lo), "=r"(hi) : "l"(v));
    return make_float2(__uint_as_float(lo), __uint_as_float(hi));
}

// 8x8 register tile FMA step: aRow -> 8 consecutive floats, bRow -> 8 consecutive floats
__device__ __forceinline__ void tile_fma(unsigned long long acc[8][4],
                                         const float* aRow, const float* bRow) {
    float4 a0 = *(const float4*)(aRow);
    float4 a1 = *(const float4*)(aRow + 4);
    ulonglong2 b0 = *(const ulonglong2*)(bRow);
    ulonglong2 b1 = *(const ulonglong2*)(bRow + 4);
    unsigned long long ap[8];
    ap[0] = pack2(a0.x); ap[1] = pack2(a0.y); ap[2] = pack2(a0.z); ap[3] = pack2(a0.w);
    ap[4] = pack2(a1.x); ap[5] = pack2(a1.y); ap[6] = pack2(a1.z); ap[7] = pack2(a1.w);
    unsigned long long bp[4];
    bp[0] = b0.x; bp[1] = b0.y; bp[2] = b1.x; bp[3] = b1.y;
#pragma unroll
    for (int i = 0; i < 8; i++) {
#pragma unroll
        for (int j = 0; j < 4; j++) fma2(acc[i][j], ap[i], bp[j]);
    }
}

__device__ __forceinline__ void row_to_float4(const unsigned long long* a, float s,
                                              float4& o0, float4& o1) {
    float2 p0 = unpack2(a[0]), p1 = unpack2(a[1]);
    float2 p2 = unpack2(a[2]), p3 = unpack2(a[3]);
    o0 = make_float4(p0.x * s, p0.y * s, p1.x * s, p1.y * s);
    o1 = make_float4(p2.x * s, p2.y * s, p3.x * s, p3.y * s);
}

// ---------------- kernel 1: transpose Wp3 ------------------------------------
__global__ void k_wp3t(const float* __restrict__ w) {
    int idx = blockIdx.x * 1024 + threadIdx.x;   // 64 blocks x 1024 = 65536
    int k = idx >> 8, c = idx & 255;
    g_wp3t[k][c] = w[c * 256 + k];
}

// ---------------- kernel 2: per-channel row sums -----------------------------
__global__ void k_rowsum(const float* __restrict__ x) {
    int n = blockIdx.y;
    int w = threadIdx.x >> 5, lane = threadIdx.x & 31;
    int c = blockIdx.x * 8 + w;
    const float* row = x + ((size_t)n * CC + c) * HW;
    float s = 0.f;
    for (int i = lane; i < HW; i += 32) s += row[i];
#pragma unroll
    for (int o = 16; o; o >>= 1) s += __shfl_down_sync(0xffffffffu, s, o);
    if (lane == 0) g_rowsum[n][c] = s;
}

// ---------------- kernel 3: Gram = x x^T per batch (K-split by 2) ------------
__global__ __launch_bounds__(256, 2) void k_gram(const float* __restrict__ x) {
    __shared__ float As[32][128];
    __shared__ float Bs[32][128];
    const int n  = blockIdx.z >> 1;
    const int ks = blockIdx.z & 1;
    const int c0 = blockIdx.y * 128;
    const int d0 = blockIdx.x * 128;
    const float* xb = x + (size_t)n * CC * HW;

    const int tid  = threadIdx.x;
    const int ty8  = (tid >> 4) * 8;   // row tile base within 128
    const int tx8  = (tid & 15) * 8;   // col tile base within 128
    const int lrow = tid & 127;        // load: which of the 128 rows
    const int lk   = (tid >> 7) * 16;  // load: k base (0 or 16)

    unsigned long long acc[8][4];
#pragma unroll
    for (int i = 0; i < 8; i++)
#pragma unroll
        for (int j = 0; j < 4; j++) acc[i][j] = 0ull;

    const int kbeg = ks * (HW / 2);
    const int kend = kbeg + (HW / 2);
    for (int k0 = kbeg; k0 < kend; k0 += 32) {
        float4 av[4], bv[4];
        const float* pa = xb + (size_t)(c0 + lrow) * HW + k0 + lk;
        const float* pb = xb + (size_t)(d0 + lrow) * HW + k0 + lk;
#pragma unroll
        for (int q = 0; q < 4; q++) {
            av[q] = *(const float4*)(pa + 4 * q);
            bv[q] = *(const float4*)(pb + 4 * q);
        }
        __syncthreads();
#pragma unroll
        for (int q = 0; q < 4; q++) {
            As[lk + 4 * q + 0][lrow] = av[q].x;
            As[lk + 4 * q + 1][lrow] = av[q].y;
            As[lk + 4 * q + 2][lrow] = av[q].z;
            As[lk + 4 * q + 3][lrow] = av[q].w;
            Bs[lk + 4 * q + 0][lrow] = bv[q].x;
            Bs[lk + 4 * q + 1][lrow] = bv[q].y;
            Bs[lk + 4 * q + 2][lrow] = bv[q].z;
            Bs[lk + 4 * q + 3][lrow] = bv[q].w;
        }
        __syncthreads();
#pragma unroll 8
        for (int k = 0; k < 32; k++)
            tile_fma(acc, &As[k][ty8], &Bs[k][tx8]);
    }

    float* gout = &g_gramp[ks][n][0][0];
#pragma unroll
    for (int i = 0; i < 8; i++) {
        int c = c0 + ty8 + i;
        float4 o0, o1;
        row_to_float4(acc[i], 1.0f, o0, o1);
        *(float4*)(gout + (size_t)c * CC + d0 + tx8)     = o0;
        *(float4*)(gout + (size_t)c * CC + d0 + tx8 + 4) = o1;
    }
}

// ---------------- kernel 4: t7 = p7w .* (B1 G B2^T + bias terms) / 56 --------
__global__ void k_t7(const float* __restrict__ Wg1, const float* __restrict__ bg1,
                     const float* __restrict__ Wg2, const float* __restrict__ bg2,
                     const float* __restrict__ p7w) {
    __shared__ float W1s[32][33], W2s[32][33], Gs[32][33], Ms[32][33];
    const int n = blockIdx.z, g = blockIdx.y, h = blockIdx.x;
    const int tx = threadIdx.x, ty = threadIdx.y;

    W1s[ty][tx] = Wg1[(g * 32 + ty) * 32 + tx];
    W2s[ty][tx] = Wg2[(h * 32 + ty) * 32 + tx];
    Gs[ty][tx]  = g_gramp[0][n][g * 32 + ty][h * 32 + tx]
                + g_gramp[1][n][g * 32 + ty][h * 32 + tx];
    __syncthreads();

    float m = 0.f;
#pragma unroll
    for (int i = 0; i < 32; i++) m += W1s[ty][i] * Gs[i][tx];

    float u = 0.f, v = 0.f;
#pragma unroll
    for (int i = 0; i < 32; i++) {
        u += W1s[ty][i] * g_rowsum[n][g * 32 + i];
        v += W2s[tx][i] * g_rowsum[n][h * 32 + i];
    }
    Ms[ty][tx] = m;
    __syncthreads();

    float t5 = 0.f;
#pragma unroll
    for (int j = 0; j < 32; j++) t5 += Ms[ty][j] * W2s[tx][j];

    const int c = g * 32 + ty, d = h * 32 + tx;
    const float b1 = bg1[c], b2 = bg2[d];
    t5 += b1 * v + u * b2 + (float)HW * b1 * b2;
    g_t7[n][c][d] = p7w[c * 256 + d] * t5 * (1.0f / 56.0f);
}

// ---------------- kernel 5: fused t3 / sin / max / output GEMM ---------------
// per block: 64-column stripe of one batch.
// stage 1: t6s[c][j] = max( (Wp3 x)[c,j] + bp3[c], sin(pi/2 * x[c,j]) )
// stage 2: out[d][j] = (1/16) * sum_c t7[n][c][d] * t6s[c][j]
#define SMEM_FUSED_BYTES ((256 * 64 + 16 * 256 + 16 * 64) * 4)

__global__ __launch_bounds__(256, 2) void k_fused(const float* __restrict__ x,
                                                  const float* __restrict__ bp3,
                                                  float* __restrict__ out) {
    extern __shared__ float sm[];
    float (*t6s)[64]  = (float(*)[64])sm;                         // 256 x 64
    float (*As)[256]  = (float(*)[256])(sm + 256 * 64);           // 16 x 256
    float (*Bs)[64]   = (float(*)[64])(sm + 256 * 64 + 16 * 256); // 16 x 64

    const int n    = blockIdx.y;
    const int col0 = blockIdx.x * 64;
    const float* xb = x + (size_t)n * CC * HW;

    const int tid = threadIdx.x;
    const int ty8 = (tid >> 3) * 8;   // output-row tile base (0..248)
    const int tx8 = (tid & 7) * 8;    // output-col tile base (0..56)
    const int ar  = tid >> 4;         // A-chunk load row (0..15)
    const int ac  = (tid & 15) * 4;   // A-chunk load col base
    const int br  = tid >> 4;         // B-chunk load row
    const int bc  = (tid & 15) * 4;   // B-chunk load col base

    unsigned long long acc[8][4];
#pragma unroll
    for (int i = 0; i < 8; i++)
#pragma unroll
        for (int j = 0; j < 4; j++) acc[i][j] = 0ull;

    // ---------------- stage 1: t3 = Wp3 @ x(stripe); sin written alongside ----
    for (int kc = 0; kc < 16; kc++) {
        const int k0 = kc * 16;
        float4 a4[4];
#pragma unroll
        for (int q = 0; q < 4; q++)
            a4[q] = *(const float4*)(&g_wp3t[k0 + ar][ac + 64 * q]);
        float4 b4 = *(const float4*)(xb + (size_t)(k0 + br) * HW + col0 + bc);
        __syncthreads();
#pragma unroll
        for (int q = 0; q < 4; q++)
            *(float4*)&As[ar][ac + 64 * q] = a4[q];
        *(float4*)&Bs[br][bc] = b4;
        float4 s4;
        s4.x = sinf(b4.x * PI_HALF);
        s4.y = sinf(b4.y * PI_HALF);
        s4.z = sinf(b4.z * PI_HALF);
        s4.w = sinf(b4.w * PI_HALF);
        *(float4*)&t6s[k0 + br][bc] = s4;
        __syncthreads();
#pragma unroll 8
        for (int k = 0; k < 16; k++)
            tile_fma(acc, &As[k][ty8], &Bs[k][tx8]);
    }

    // epilogue: t6 = max(t3 + bp3, sin)  (each thread owns exclusive cells)
#pragma unroll
    for (int i = 0; i < 8; i++) {
        const int c = ty8 + i;
        const float bias = __ldg(&bp3[c]);
#pragma unroll
        for (int j = 0; j < 4; j++) {
            float2 p = unpack2(acc[i][j]);
            float* t = &t6s[c][tx8 + 2 * j];
            t[0] = fmaxf(t[0], p.x + bias);
            t[1] = fmaxf(t[1], p.y + bias);
            acc[i][j] = 0ull;
        }
    }
    __syncthreads();

    // ---------------- stage 2: out = (1/16) t7^T @ t6 -------------------------
    const float* t7b = &g_t7[n][0][0];
    for (int kc = 0; kc < 16; kc++) {
        const int k0 = kc * 16;
        float4 a4[4];
#pragma unroll
        for (int q = 0; q < 4; q++)
            a4[q] = *(const float4*)(t7b + (size_t)(k0 + ar) * 256 + ac + 64 * q);
        __syncthreads();
#pragma unroll
        for (int q = 0; q < 4; q++)
            *(float4*)&As[ar][ac + 64 * q] = a4[q];
        __syncthreads();
#pragma unroll 8
        for (int k = 0; k < 16; k++)
            tile_fma(acc, &As[k][ty8], &t6s[k0 + k][tx8]);
    }

    float* ob = out + (size_t)n * CC * HW;
#pragma unroll
    for (int i = 0; i < 8; i++) {
        const int d = ty8 + i;
        float4 o0, o1;
        row_to_float4(acc[i], 1.0f / 16.0f, o0, o1);
        *(float4*)(ob + (size_t)d * HW + col0 + tx8)     = o0;
        *(float4*)(ob + (size_t)d * HW + col0 + tx8 + 4) = o1;
    }
}

// ---------------- launch ------------------------------------------------------
extern "C" void kernel_launch(void* const* d_in, const int* in_sizes, int n_in,
                              void* d_out, int out_size) {
    (void)in_sizes; (void)n_in; (void)out_size;
    const float* x   = (const float*)d_in[0];
    const float* Wp3 = (const float*)d_in[1];
    const float* bp3 = (const float*)d_in[2];
    const float* Wg1 = (const float*)d_in[3];
    const float* bg1 = (const float*)d_in[4];
    const float* Wg2 = (const float*)d_in[5];
    const float* bg2 = (const float*)d_in[6];
    const float* p7w = (const float*)d_in[7];
    float* out = (float*)d_out;

    cudaFuncSetAttribute(k_fused, cudaFuncAttributeMaxDynamicSharedMemorySize,
                         SMEM_FUSED_BYTES);

    k_wp3t<<<64, 1024>>>(Wp3);
    k_rowsum<<<dim3(32, 32), 256>>>(x);
    k_gram<<<dim3(2, 2, 64), 256>>>(x);
    k_t7<<<dim3(8, 8, 32), dim3(32, 32)>>>(Wg1, bg1, Wg2, bg2, p7w);
    k_fused<<<dim3(49, 32), 256, SMEM_FUSED_BYTES>>>(x, bp3, out);
}

// round 4
// speedup vs baseline: 1.8578x; 1.8573x over previous
#include <cuda_runtime.h>
#include <cuda_bf16.h>
#include <stdint.h>
#include <math.h>

#define NB 32
#define CC 256
#define HW 3136
#define PI_HALF 1.57079632679489662f

__device__ __nv_bfloat16 g_xh[NB][CC][HW];
__device__ __nv_bfloat16 g_xl[NB][CC][HW];
__device__ float g_gram[NB][CC][CC];
__device__ float g_rowsum[NB][CC];
__device__ float g_u[NB][CC];
__device__ float g_v[NB][CC];
__device__ __nv_bfloat16 g_wph[CC][CC];
__device__ __nv_bfloat16 g_wpl[CC][CC];
__device__ __nv_bfloat16 g_t7h[NB][CC][CC];   // t7^T [d][c], bf16 hi
__device__ __nv_bfloat16 g_t7l[NB][CC][CC];   // t7^T [d][c], bf16 lo

__device__ __forceinline__ uint32_t smem_u32(const void* p) {
    uint32_t a;
    asm("{ .reg .u64 t; cvta.to.shared.u64 t, %1; cvt.u32.u64 %0, t; }"
        : "=r"(a) : "l"(p));
    return a;
}
__device__ __forceinline__ void ldsm4(uint32_t r[4], uint32_t a) {
    asm volatile("ldmatrix.sync.aligned.m8n8.x4.shared.b16 {%0,%1,%2,%3}, [%4];"
                 : "=r"(r[0]), "=r"(r[1]), "=r"(r[2]), "=r"(r[3]) : "r"(a));
}
__device__ __forceinline__ void ldsm4t(uint32_t r[4], uint32_t a) {
    asm volatile("ldmatrix.sync.aligned.m8n8.x4.trans.shared.b16 {%0,%1,%2,%3}, [%4];"
                 : "=r"(r[0]), "=r"(r[1]), "=r"(r[2]), "=r"(r[3]) : "r"(a));
}
__device__ __forceinline__ void mma_bf16(float c[4], const uint32_t a[4],
                                         const uint32_t b[2]) {
    asm volatile(
        "mma.sync.aligned.m16n8k16.row.col.f32.bf16.bf16.f32 "
        "{%0,%1,%2,%3}, {%4,%5,%6,%7}, {%8,%9}, {%0,%1,%2,%3};"
        : "+f"(c[0]), "+f"(c[1]), "+f"(c[2]), "+f"(c[3])
        : "r"(a[0]), "r"(a[1]), "r"(a[2]), "r"(a[3]), "r"(b[0]), "r"(b[1]));
}
__device__ __forceinline__ uint32_t pk2(__nv_bfloat16 a, __nv_bfloat16 b) {
    unsigned short ua = *(unsigned short*)&a, ub = *(unsigned short*)&b;
    return (uint32_t)ua | ((uint32_t)ub << 16);
}
__device__ __forceinline__ float bflo(uint32_t v) {
    unsigned short u = (unsigned short)(v & 0xffffu);
    return __bfloat162float(*(__nv_bfloat16*)&u);
}
__device__ __forceinline__ float bfhi(uint32_t v) {
    unsigned short u = (unsigned short)(v >> 16);
    return __bfloat162float(*(__nv_bfloat16*)&u);
}

// ---- prep: x -> bf16 hi/lo + rowsums ----------------------------------------
__global__ void k_prep(const float* __restrict__ x) {
    const int n = blockIdx.y, c = blockIdx.x, t = threadIdx.x;
    const float4* row = (const float4*)(x + ((size_t)n * CC + c) * HW);
    uint2* oh = (uint2*)&g_xh[n][c][0];
    uint2* ol = (uint2*)&g_xl[n][c][0];
    float s = 0.f;
    for (int u = t; u < HW / 4; u += 256) {
        float4 v = row[u];
        s += v.x + v.y + v.z + v.w;
        __nv_bfloat16 h0 = __float2bfloat16(v.x), h1 = __float2bfloat16(v.y);
        __nv_bfloat16 h2 = __float2bfloat16(v.z), h3 = __float2bfloat16(v.w);
        uint2 ph, pl;
        ph.x = pk2(h0, h1); ph.y = pk2(h2, h3);
        pl.x = pk2(__float2bfloat16(v.x - __bfloat162float(h0)),
                   __float2bfloat16(v.y - __bfloat162float(h1)));
        pl.y = pk2(__float2bfloat16(v.z - __bfloat162float(h2)),
                   __float2bfloat16(v.w - __bfloat162float(h3)));
        oh[u] = ph; ol[u] = pl;
    }
#pragma unroll
    for (int o = 16; o; o >>= 1) s += __shfl_down_sync(0xffffffffu, s, o);
    __shared__ float red[8];
    if ((t & 31) == 0) red[t >> 5] = s;
    __syncthreads();
    if (t == 0) {
        float tt = 0.f;
#pragma unroll
        for (int q = 0; q < 8; q++) tt += red[q];
        g_rowsum[n][c] = tt;
    }
}

__global__ void k_wprep(const float* __restrict__ w) {
    const int o = blockIdx.x, i = threadIdx.x;
    const float v = w[o * 256 + i];
    __nv_bfloat16 h = __float2bfloat16(v);
    g_wph[o][i] = h;
    g_wpl[o][i] = __float2bfloat16(v - __bfloat162float(h));
}

__global__ void k_uv(const float* __restrict__ Wg1, const float* __restrict__ Wg2) {
    const int n = blockIdx.x, t = threadIdx.x;
    __shared__ float ss[256];
    ss[t] = g_rowsum[n][t];
    __syncthreads();
    const int g = t >> 5, r = t & 31;
    float u = 0.f, v = 0.f;
#pragma unroll
    for (int i = 0; i < 32; i++) {
        u += Wg1[(g * 32 + r) * 32 + i] * ss[g * 32 + i];
        v += Wg2[(g * 32 + r) * 32 + i] * ss[g * 32 + i];
    }
    g_u[n][t] = u;
    g_v[n][t] = v;
}

// ---- Gram = x x^T via mma.sync bf16 split ------------------------------------
#define GSTRIDE 80u
#define GCH 10240
#define GRAM_SMEM (8 * GCH)

__global__ __launch_bounds__(256, 1) void k_gram() {
    extern __shared__ char sm[];
    const int n = blockIdx.y;
    const int c0 = (blockIdx.x & 1) * 128, d0 = (blockIdx.x >> 1) * 128;
    const int tid = threadIdx.x, lane = tid & 31, wid = tid >> 5;
    const int m0w = (wid & 1) * 64, n0w = (wid >> 1) * 32;
    const uint32_t smb = smem_u32(sm);

    const char* gAh = (const char*)&g_xh[n][c0][0];
    const char* gAl = (const char*)&g_xl[n][c0][0];
    const char* gBh = (const char*)&g_xh[n][d0][0];
    const char* gBl = (const char*)&g_xl[n][d0][0];

    const int lr = tid >> 1, ls = (tid & 1) * 32;
    const int a_r = lane & 15, a_kb = (lane >> 4) * 16;
    const int b_r = (lane & 7) + 8 * (lane >> 4);
    const int b_kb = ((lane >> 3) & 1) * 16;

    float acc[4][4][4];
#pragma unroll
    for (int i = 0; i < 4; i++)
#pragma unroll
        for (int j = 0; j < 4; j++)
#pragma unroll
            for (int q = 0; q < 4; q++) acc[i][j][q] = 0.f;

    uint4 v[8];
    auto ldregs = [&](int k0) {
        const size_t go = (size_t)lr * (HW * 2) + (size_t)k0 * 2 + ls;
        v[0] = *(const uint4*)(gAh + go); v[1] = *(const uint4*)(gAh + go + 16);
        v[2] = *(const uint4*)(gAl + go); v[3] = *(const uint4*)(gAl + go + 16);
        v[4] = *(const uint4*)(gBh + go); v[5] = *(const uint4*)(gBh + go + 16);
        v[6] = *(const uint4*)(gBl + go); v[7] = *(const uint4*)(gBl + go + 16);
    };
    auto stchunk = [&](int buf) {
        const uint32_t so = (uint32_t)lr * GSTRIDE + ls;
        char* pAh = sm + (buf * 2 + 0) * GCH;
        char* pAl = sm + (buf * 2 + 1) * GCH;
        char* pBh = sm + 4 * GCH + (buf * 2 + 0) * GCH;
        char* pBl = sm + 4 * GCH + (buf * 2 + 1) * GCH;
        *(uint4*)(pAh + so) = v[0]; *(uint4*)(pAh + so + 16) = v[1];
        *(uint4*)(pAl + so) = v[2]; *(uint4*)(pAl + so + 16) = v[3];
        *(uint4*)(pBh + so) = v[4]; *(uint4*)(pBh + so + 16) = v[5];
        *(uint4*)(pBl + so) = v[6]; *(uint4*)(pBl + so + 16) = v[7];
    };

    ldregs(0);
    stchunk(0);
    __syncthreads();

    for (int ci = 0; ci < 98; ci++) {
        const int buf = ci & 1;
        if (ci + 1 < 98) ldregs((ci + 1) * 32);
        const uint32_t aHb = smb + (buf * 2 + 0) * GCH;
        const uint32_t aLb = smb + (buf * 2 + 1) * GCH;
        const uint32_t bHb = smb + 4 * GCH + (buf * 2 + 0) * GCH;
        const uint32_t bLb = smb + 4 * GCH + (buf * 2 + 1) * GCH;
#pragma unroll
        for (int kk = 0; kk < 2; kk++) {
            const uint32_t kbo = kk * 32;
            uint32_t ah[4][4], al[4][4], bh[4][2], bl[4][2];
#pragma unroll
            for (int mt = 0; mt < 4; mt++) {
                uint32_t ro = (uint32_t)(m0w + mt * 16 + a_r) * GSTRIDE + a_kb + kbo;
                ldsm4(ah[mt], aHb + ro);
                ldsm4(al[mt], aLb + ro);
            }
#pragma unroll
            for (int nt2 = 0; nt2 < 2; nt2++) {
                uint32_t ro = (uint32_t)(n0w + nt2 * 16 + b_r) * GSTRIDE + b_kb + kbo;
                uint32_t t[4];
                ldsm4(t, bHb + ro);
                bh[nt2 * 2][0] = t[0]; bh[nt2 * 2][1] = t[1];
                bh[nt2 * 2 + 1][0] = t[2]; bh[nt2 * 2 + 1][1] = t[3];
                ldsm4(t, bLb + ro);
                bl[nt2 * 2][0] = t[0]; bl[nt2 * 2][1] = t[1];
                bl[nt2 * 2 + 1][0] = t[2]; bl[nt2 * 2 + 1][1] = t[3];
            }
#pragma unroll
            for (int mt = 0; mt < 4; mt++)
#pragma unroll
                for (int nt = 0; nt < 4; nt++) {
                    mma_bf16(acc[mt][nt], ah[mt], bh[nt]);
                    mma_bf16(acc[mt][nt], ah[mt], bl[nt]);
                    mma_bf16(acc[mt][nt], al[mt], bh[nt]);
                }
        }
        if (ci + 1 < 98) stchunk(buf ^ 1);
        __syncthreads();
    }

    float* gout = &g_gram[n][0][0];
#pragma unroll
    for (int mt = 0; mt < 4; mt++)
#pragma unroll
        for (int h = 0; h < 2; h++) {
            const int c = c0 + m0w + mt * 16 + (lane >> 2) + h * 8;
#pragma unroll
            for (int nt = 0; nt < 4; nt++) {
                const int d = d0 + n0w + nt * 8 + (lane & 3) * 2;
                *(float2*)(gout + (size_t)c * CC + d) =
                    make_float2(acc[mt][nt][h * 2], acc[mt][nt][h * 2 + 1]);
            }
        }
}

// ---- t7^T (split bf16, pre-scaled by 1/(56*16)) ------------------------------
__global__ void k_t7(const float* __restrict__ Wg1, const float* __restrict__ bg1,
                     const float* __restrict__ Wg2, const float* __restrict__ bg2,
                     const float* __restrict__ p7w) {
    __shared__ float W1s[32][33], W2s[32][33], Gs[32][33], Ms[32][33];
    const int n = blockIdx.z, g = blockIdx.y, h = blockIdx.x;
    const int tx = threadIdx.x, ty = threadIdx.y;

    W1s[ty][tx] = Wg1[(g * 32 + ty) * 32 + tx];
    W2s[ty][tx] = Wg2[(h * 32 + ty) * 32 + tx];
    Gs[ty][tx]  = g_gram[n][g * 32 + ty][h * 32 + tx];
    __syncthreads();

    float m = 0.f;
#pragma unroll
    for (int i = 0; i < 32; i++) m += W1s[ty][i] * Gs[i][tx];
    Ms[ty][tx] = m;
    __syncthreads();

    float t5 = 0.f;
#pragma unroll
    for (int j = 0; j < 32; j++) t5 += Ms[ty][j] * W2s[tx][j];

    const int c = g * 32 + ty, d = h * 32 + tx;
    const float b1 = bg1[c], b2 = bg2[d];
    t5 += b1 * g_v[n][d] + g_u[n][c] * b2 + (float)HW * b1 * b2;
    const float val = p7w[c * 256 + d] * t5 * (1.0f / 896.0f);

    __syncthreads();
    W1s[ty][tx] = val;
    __syncthreads();
    const float tv = W1s[tx][ty];
    const int dd = h * 32 + ty, cc = g * 32 + tx;
    __nv_bfloat16 hh = __float2bfloat16(tv);
    g_t7h[n][dd][cc] = hh;
    g_t7l[n][dd][cc] = __float2bfloat16(tv - __bfloat162float(hh));
}

// ---- fused: t3 mma -> max/sin -> out mma ------------------------------------
#define FLDB 144u
#define FBX 36864
#define FSTRIDE 80u
#define FACH 20480
#define FUSED_SMEM (2 * FBX + 4 * FACH)

__global__ __launch_bounds__(256, 1) void k_fused(const float* __restrict__ bp3,
                                                  float* __restrict__ out) {
    extern __shared__ char sm[];
    const int n = blockIdx.y, sx = blockIdx.x;
    const int tid = threadIdx.x, lane = tid & 31, wid = tid >> 5;
    const int m0w = (wid >> 1) * 64, n0w = (wid & 1) * 32;
    const uint32_t smb = smem_u32(sm);

    {   // Bx = x stripe [256 rows(k)][64 cols] hi/lo
        const char* srcH = (const char*)&g_xh[n][0][sx * 64];
        const char* srcL = (const char*)&g_xl[n][0][sx * 64];
#pragma unroll
        for (int i = 0; i < 8; i++) {
            const int idx = tid + i * 256;
            const int r = idx >> 3, s = (idx & 7) * 16;
            *(uint4*)(sm + r * FLDB + s)       = *(const uint4*)(srcH + (size_t)r * (HW * 2) + s);
            *(uint4*)(sm + FBX + r * FLDB + s) = *(const uint4*)(srcL + (size_t)r * (HW * 2) + s);
        }
    }

    float acc[4][4][4];
#pragma unroll
    for (int i = 0; i < 4; i++)
#pragma unroll
        for (int j = 0; j < 4; j++)
#pragma unroll
            for (int q = 0; q < 4; q++) acc[i][j][q] = 0.f;

    const int a_r = lane & 15, a_kb = (lane >> 4) * 16;
    const int bt_r = (lane & 7) + 8 * ((lane >> 3) & 1);
    const int bt_nb = (lane >> 4) * 16;
    __syncthreads();

    for (int stage = 0; stage < 2; stage++) {
        const char* Ah = stage ? (const char*)&g_t7h[n][0][0] : (const char*)&g_wph[0][0];
        const char* Al = stage ? (const char*)&g_t7l[n][0][0] : (const char*)&g_wpl[0][0];

        uint4 v[8];
        auto ldA = [&](int k0) {
#pragma unroll
            for (int i = 0; i < 4; i++) {
                const int idx = tid + i * 256;
                const int r = idx >> 2, s = (idx & 3) * 16;
                v[i]     = *(const uint4*)(Ah + (size_t)r * 512 + k0 * 2 + s);
                v[4 + i] = *(const uint4*)(Al + (size_t)r * 512 + k0 * 2 + s);
            }
        };
        auto stA = [&](int buf) {
            char* pH = sm + 2 * FBX + (buf * 2 + 0) * FACH;
            char* pL = sm + 2 * FBX + (buf * 2 + 1) * FACH;
#pragma unroll
            for (int i = 0; i < 4; i++) {
                const int idx = tid + i * 256;
                const int r = idx >> 2, s = (idx & 3) * 16;
                *(uint4*)(pH + r * FSTRIDE + s) = v[i];
                *(uint4*)(pL + r * FSTRIDE + s) = v[4 + i];
            }
        };

        ldA(0); stA(0);
        __syncthreads();
        for (int ci = 0; ci < 8; ci++) {
            const int buf = ci & 1;
            if (ci + 1 < 8) ldA((ci + 1) * 32);
            const uint32_t aHb = smb + 2 * FBX + (buf * 2 + 0) * FACH;
            const uint32_t aLb = smb + 2 * FBX + (buf * 2 + 1) * FACH;
#pragma unroll
            for (int kk = 0; kk < 2; kk++) {
                uint32_t ah[4][4], al[4][4], bh[4][2], bl[4][2];
#pragma unroll
                for (int mt = 0; mt < 4; mt++) {
                    uint32_t ro = (uint32_t)(m0w + mt * 16 + a_r) * FSTRIDE + kk * 32 + a_kb;
                    ldsm4(ah[mt], aHb + ro);
                    ldsm4(al[mt], aLb + ro);
                }
                const int kg = ci * 32 + kk * 16;
#pragma unroll
                for (int nt2 = 0; nt2 < 2; nt2++) {
                    uint32_t ro = (uint32_t)(kg + bt_r) * FLDB + (n0w + nt2 * 16) * 2 + bt_nb;
                    uint32_t t[4];
                    ldsm4t(t, smb + ro);
                    bh[nt2 * 2][0] = t[0]; bh[nt2 * 2][1] = t[1];
                    bh[nt2 * 2 + 1][0] = t[2]; bh[nt2 * 2 + 1][1] = t[3];
                    ldsm4t(t, smb + FBX + ro);
                    bl[nt2 * 2][0] = t[0]; bl[nt2 * 2][1] = t[1];
                    bl[nt2 * 2 + 1][0] = t[2]; bl[nt2 * 2 + 1][1] = t[3];
                }
#pragma unroll
                for (int mt = 0; mt < 4; mt++)
#pragma unroll
                    for (int nt = 0; nt < 4; nt++) {
                        mma_bf16(acc[mt][nt], ah[mt], bh[nt]);
                        mma_bf16(acc[mt][nt], ah[mt], bl[nt]);
                        mma_bf16(acc[mt][nt], al[mt], bh[nt]);
                    }
            }
            if (ci + 1 < 8) stA(buf ^ 1);
            __syncthreads();
        }

        if (stage == 0) {
            // t6 = max(t3 + bias, sin(pi/2 x)); overwrite Bx with t6 hi/lo
#pragma unroll
            for (int mt = 0; mt < 4; mt++)
#pragma unroll
                for (int h = 0; h < 2; h++) {
                    const int c = m0w + mt * 16 + (lane >> 2) + h * 8;
                    const float bias = __ldg(&bp3[c]);
#pragma unroll
                    for (int nt = 0; nt < 4; nt++) {
                        const int j = n0w + nt * 8 + (lane & 3) * 2;
                        uint32_t ph = *(uint32_t*)(sm + c * FLDB + j * 2);
                        uint32_t pl = *(uint32_t*)(sm + FBX + c * FLDB + j * 2);
                        const float x0 = bflo(ph) + bflo(pl);
                        const float x1 = bfhi(ph) + bfhi(pl);
                        const float t60 = fmaxf(acc[mt][nt][h * 2] + bias,
                                                sinf(PI_HALF * x0));
                        const float t61 = fmaxf(acc[mt][nt][h * 2 + 1] + bias,
                                                sinf(PI_HALF * x1));
                        __nv_bfloat16 h0 = __float2bfloat16(t60);
                        __nv_bfloat16 h1 = __float2bfloat16(t61);
                        *(uint32_t*)(sm + c * FLDB + j * 2) = pk2(h0, h1);
                        *(uint32_t*)(sm + FBX + c * FLDB + j * 2) =
                            pk2(__float2bfloat16(t60 - __bfloat162float(h0)),
                                __float2bfloat16(t61 - __bfloat162float(h1)));
                        acc[mt][nt][h * 2] = 0.f;
                        acc[mt][nt][h * 2 + 1] = 0.f;
                    }
                }
            __syncthreads();
        }
    }

    float* ob = out + (size_t)n * CC * HW + sx * 64;
#pragma unroll
    for (int mt = 0; mt < 4; mt++)
#pragma unroll
        for (int h = 0; h < 2; h++) {
            const int d = m0w + mt * 16 + (lane >> 2) + h * 8;
#pragma unroll
            for (int nt = 0; nt < 4; nt++) {
                const int j = n0w + nt * 8 + (lane & 3) * 2;
                *(float2*)(ob + (size_t)d * HW + j) =
                    make_float2(acc[mt][nt][h * 2], acc[mt][nt][h * 2 + 1]);
            }
        }
}

extern "C" void kernel_launch(void* const* d_in, const int* in_sizes, int n_in,
                              void* d_out, int out_size) {
    (void)in_sizes; (void)n_in; (void)out_size;
    const float* x   = (const float*)d_in[0];
    const float* Wp3 = (const float*)d_in[1];
    const float* bp3 = (const float*)d_in[2];
    const float* Wg1 = (const float*)d_in[3];
    const float* bg1 = (const float*)d_in[4];
    const float* Wg2 = (const float*)d_in[5];
    const float* bg2 = (const float*)d_in[6];
    const float* p7w = (const float*)d_in[7];
    float* out = (float*)d_out;

    cudaFuncSetAttribute(k_gram,  cudaFuncAttributeMaxDynamicSharedMemorySize, GRAM_SMEM);
    cudaFuncSetAttribute(k_fused, cudaFuncAttributeMaxDynamicSharedMemorySize, FUSED_SMEM);

    k_wprep<<<256, 256>>>(Wp3);
    k_prep<<<dim3(256, 32), 256>>>(x);
    k_uv<<<32, 256>>>(Wg1, Wg2);
    k_gram<<<dim3(4, 32), 256, GRAM_SMEM>>>();
    k_t7<<<dim3(8, 8, 32), dim3(32, 32)>>>(Wg1, bg1, Wg2, bg2, p7w);
    k_fused<<<dim3(49, 32), 256, FUSED_SMEM>>>(bp3, out);
}